// round 1
// baseline (speedup 1.0000x reference)
#include <cuda_runtime.h>
#include <math.h>

#define BB 8
#define VV 3
#define HH 512
#define WW 640
#define NPIX (HH*WW)
#define NPAIR (VV*VV)
#define BX 160
#define TPB 256

__device__ float  g_P[BB*NPAIR*16];
__device__ double g_num[NPAIR];
__device__ double g_den[NPAIR];

__device__ __forceinline__ void mat4mul(const float* A, const float* Bm, float* C) {
#pragma unroll
    for (int r = 0; r < 4; r++)
#pragma unroll
        for (int c = 0; c < 4; c++) {
            float s = 0.0f;
#pragma unroll
            for (int k = 0; k < 4; k++) s = fmaf(A[r*4+k], Bm[k*4+c], s);
            C[r*4+c] = s;
        }
}

// Compute P[b,i,j] = K[b] @ RT[b,j] @ inv(RT[b,i]) @ inv(K[b]) and zero accumulators.
__global__ void setup_kernel(const float* __restrict__ K, const float* __restrict__ RT) {
    int t = threadIdx.x;
    if (t < NPAIR) { g_num[t] = 0.0; g_den[t] = 0.0; }
    if (t >= BB*NPAIR) return;
    int b = t / NPAIR, p = t % NPAIR, i = p / VV, j = p % VV;

    const float* Kb  = K  + b*16;
    const float* RTi = RT + (b*VV + i)*16;
    const float* RTj = RT + (b*VV + j)*16;

    // K^{-1}: K = [[fx,0,cx,0],[0,fy,cy,0],[0,0,1,0],[0,0,0,1]]
    float Kinv[16] = {0};
    float fx = Kb[0], fy = Kb[5], cx = Kb[2], cy = Kb[6];
    Kinv[0]  = 1.0f/fx;  Kinv[2]  = -cx/fx;
    Kinv[5]  = 1.0f/fy;  Kinv[6]  = -cy/fy;
    Kinv[10] = 1.0f;     Kinv[15] = 1.0f;

    // RT_i^{-1} = [R^T, -R^T t; 0 0 0 1]  (R orthogonal)
    float Ri[16] = {0};
    Ri[0] = RTi[0]; Ri[1] = RTi[4]; Ri[2]  = RTi[8];
    Ri[4] = RTi[1]; Ri[5] = RTi[5]; Ri[6]  = RTi[9];
    Ri[8] = RTi[2]; Ri[9] = RTi[6]; Ri[10] = RTi[10];
    float tx = RTi[3], ty = RTi[7], tz = RTi[11];
    Ri[3]  = -(Ri[0]*tx + Ri[1]*ty + Ri[2]*tz);
    Ri[7]  = -(Ri[4]*tx + Ri[5]*ty + Ri[6]*tz);
    Ri[11] = -(Ri[8]*tx + Ri[9]*ty + Ri[10]*tz);
    Ri[15] = 1.0f;

    float M1[16], M2[16], Pf[16];
    mat4mul(RTj, Ri, M1);
    mat4mul(M1, Kinv, M2);
    mat4mul(Kb, M2, Pf);
#pragma unroll
    for (int k = 0; k < 16; k++) g_P[t*16 + k] = Pf[k];
}

__device__ __forceinline__ float corner(const float* __restrict__ img, int xi, int yi) {
    if ((unsigned)xi < (unsigned)WW && (unsigned)yi < (unsigned)HH)
        return __ldg(img + yi*WW + xi);
    return 0.0f;
}

__global__ void __launch_bounds__(TPB)
loss_kernel(const float* __restrict__ pred) {
    const int p = blockIdx.z, b = blockIdx.y;
    const int i = p / VV, j = p % VV;

    const float* __restrict__ Pm = g_P + (b*NPAIR + p)*16;
    const float P00 = Pm[0],  P01 = Pm[1],  P02 = Pm[2],  P03 = Pm[3];
    const float P10 = Pm[4],  P11 = Pm[5],  P12 = Pm[6],  P13 = Pm[7];
    const float P20 = Pm[8],  P21 = Pm[9],  P22 = Pm[10], P23 = Pm[11];
    const float P30 = Pm[12], P31 = Pm[13], P32 = Pm[14], P33 = Pm[15];

    const float* __restrict__ di = pred + (size_t)(b*VV + i)*NPIX;
    const float* __restrict__ dj = pred + (size_t)(b*VV + j)*NPIX;

    float num = 0.0f, den = 0.0f;

    for (int n = blockIdx.x*TPB + threadIdx.x; n < NPIX; n += BX*TPB) {
        int yi = n / WW;
        int xi = n - yi*WW;
        float xf = (float)xi, yf = (float)yi;
        float d = __ldg(di + n);

        float px = fmaf(d, fmaf(P00, xf, fmaf(P01, yf, P02)), P03);
        float py = fmaf(d, fmaf(P10, xf, fmaf(P11, yf, P12)), P13);
        float pz = fmaf(d, fmaf(P20, xf, fmaf(P21, yf, P22)), P23);
        float pw = fmaf(d, fmaf(P30, xf, fmaf(P31, yf, P32)), P33);
        float rw = 1.0f / pw;   // pw == 1 exactly by construction, kept generic
        px *= rw; py *= rw; pz *= rw;

        float gx = px * (2.0f/(float)(WW-1)) - 1.0f;
        float gy = py * (2.0f/(float)(HH-1)) - 1.0f;

        if (gx >= -1.0f && gx <= 1.0f && gy >= -1.0f && gy <= 1.0f) {
            float ix = ((gx + 1.0f)*(float)WW - 1.0f)*0.5f;
            float iy = ((gy + 1.0f)*(float)HH - 1.0f)*0.5f;
            float x0f = floorf(ix), y0f = floorf(iy);
            float wx1 = ix - x0f,   wy1 = iy - y0f;
            float wx0 = 1.0f - wx1, wy0 = 1.0f - wy1;
            int x0 = (int)x0f, y0 = (int)y0f;

            float c00 = corner(dj, x0,     y0);
            float c10 = corner(dj, x0 + 1, y0);
            float c01 = corner(dj, x0,     y0 + 1);
            float c11 = corner(dj, x0 + 1, y0 + 1);

            float warped = wy0*(wx0*c00 + wx1*c10) + wy1*(wx0*c01 + wx1*c11);
            num += fabsf(warped - pz);
            den += 1.0f;
        }
    }

    // warp reduce
#pragma unroll
    for (int o = 16; o > 0; o >>= 1) {
        num += __shfl_xor_sync(0xFFFFFFFFu, num, o);
        den += __shfl_xor_sync(0xFFFFFFFFu, den, o);
    }
    __shared__ float snum[TPB/32], sden[TPB/32];
    int warp = threadIdx.x >> 5, lane = threadIdx.x & 31;
    if (lane == 0) { snum[warp] = num; sden[warp] = den; }
    __syncthreads();
    if (warp == 0) {
        num = (lane < TPB/32) ? snum[lane] : 0.0f;
        den = (lane < TPB/32) ? sden[lane] : 0.0f;
#pragma unroll
        for (int o = 4; o > 0; o >>= 1) {
            num += __shfl_xor_sync(0xFFFFFFFFu, num, o);
            den += __shfl_xor_sync(0xFFFFFFFFu, den, o);
        }
        if (lane == 0) {
            atomicAdd(&g_num[p], (double)num);
            atomicAdd(&g_den[p], (double)den);
        }
    }
}

__global__ void finalize_kernel(float* __restrict__ out) {
    if (threadIdx.x == 0) {
        double t = 0.0;
#pragma unroll
        for (int p = 0; p < NPAIR; p++) {
            double dn = g_den[p];
            t += g_num[p] / (dn > 1.0 ? dn : 1.0);
        }
        out[0] = (float)t;
    }
}

extern "C" void kernel_launch(void* const* d_in, const int* in_sizes, int n_in,
                              void* d_out, int out_size) {
    const float* pred = (const float*)d_in[0];   // (B,V,H,W)
    const float* K    = (const float*)d_in[1];   // (B,4,4)
    const float* RT   = (const float*)d_in[2];   // (B,V,4,4)
    float* out = (float*)d_out;

    setup_kernel<<<1, 128>>>(K, RT);
    loss_kernel<<<dim3(BX, BB, NPAIR), TPB>>>(pred);
    finalize_kernel<<<1, 32>>>(out);
}

// round 2
// speedup vs baseline: 1.0291x; 1.0291x over previous
#include <cuda_runtime.h>
#include <math.h>

#define BB 8
#define VV 3
#define HH 512
#define WW 640
#define NPIX (HH*WW)
#define NPAIR (VV*VV)
#define TPB 256
#define QPT 4                      // quads (float4) per thread
#define GX 80                      // grid.x: 80*256*4 = 81920 = NPIX/4 quads
#define QSTRIDE (GX*TPB)
#define QROW (WW/4)                // 160 quads per row

__device__ float  g_P[BB*NPAIR*16];
__device__ double g_num[BB*NPAIR];
__device__ double g_den[BB*NPAIR];

__device__ __forceinline__ void mat4mul(const float* A, const float* Bm, float* C) {
#pragma unroll
    for (int r = 0; r < 4; r++)
#pragma unroll
        for (int c = 0; c < 4; c++) {
            float s = 0.0f;
#pragma unroll
            for (int k = 0; k < 4; k++) s = fmaf(A[r*4+k], Bm[k*4+c], s);
            C[r*4+c] = s;
        }
}

__global__ void setup_kernel(const float* __restrict__ K, const float* __restrict__ RT) {
    int t = threadIdx.x;
    if (t < BB*NPAIR) { g_num[t] = 0.0; g_den[t] = 0.0; }
    if (t >= BB*NPAIR) return;
    int b = t / NPAIR, p = t % NPAIR, i = p / VV, j = p % VV;

    const float* Kb  = K  + b*16;
    const float* RTi = RT + (b*VV + i)*16;
    const float* RTj = RT + (b*VV + j)*16;

    // K^{-1} closed form
    float Kinv[16] = {0};
    float fx = Kb[0], fy = Kb[5], cx = Kb[2], cy = Kb[6];
    Kinv[0]  = 1.0f/fx;  Kinv[2]  = -cx/fx;
    Kinv[5]  = 1.0f/fy;  Kinv[6]  = -cy/fy;
    Kinv[10] = 1.0f;     Kinv[15] = 1.0f;

    // RT_i^{-1} = [R^T, -R^T t] (R orthogonal from QR)
    float Ri[16] = {0};
    Ri[0] = RTi[0]; Ri[1] = RTi[4]; Ri[2]  = RTi[8];
    Ri[4] = RTi[1]; Ri[5] = RTi[5]; Ri[6]  = RTi[9];
    Ri[8] = RTi[2]; Ri[9] = RTi[6]; Ri[10] = RTi[10];
    float tx = RTi[3], ty = RTi[7], tz = RTi[11];
    Ri[3]  = -(Ri[0]*tx + Ri[1]*ty + Ri[2]*tz);
    Ri[7]  = -(Ri[4]*tx + Ri[5]*ty + Ri[6]*tz);
    Ri[11] = -(Ri[8]*tx + Ri[9]*ty + Ri[10]*tz);
    Ri[15] = 1.0f;

    float M1[16], M2[16], Pf[16];
    mat4mul(RTj, Ri, M1);
    mat4mul(M1, Kinv, M2);
    mat4mul(Kb, M2, Pf);
#pragma unroll
    for (int k = 0; k < 16; k++) g_P[t*16 + k] = Pf[k];
}

__device__ __forceinline__ float corner(const float* __restrict__ img, int xi, int yi) {
    if ((unsigned)xi < (unsigned)WW && (unsigned)yi < (unsigned)HH)
        return __ldg(img + yi*WW + xi);
    return 0.0f;
}

__global__ void __launch_bounds__(TPB)
loss_kernel(const float* __restrict__ pred) {
    const int b = blockIdx.y, i = blockIdx.z;
    const float* __restrict__ di = pred + (size_t)(b*VV + i)*NPIX;

    // Batch-load QPT float4 quads up front (MLP), decode coordinates once.
    float4 dv[QPT];
    float  yfv[QPT], xfv[QPT];
    const int q0 = blockIdx.x*TPB + threadIdx.x;
#pragma unroll
    for (int k = 0; k < QPT; k++) {
        int q = q0 + k*QSTRIDE;
        dv[k] = __ldg((const float4*)di + q);
        int yy = q / QROW;
        int xb = (q - yy*QROW) * 4;
        yfv[k] = (float)yy;
        xfv[k] = (float)xb;
    }

    float num[VV], den[VV];
#pragma unroll
    for (int j = 0; j < VV; j++) { num[j] = 0.0f; den[j] = 0.0f; }

    const float inv_hw = 1.0f/319.5f;   // 2/(W-1)
    const float inv_hh = 1.0f/255.5f;   // 2/(H-1)

#pragma unroll
    for (int j = 0; j < VV; j++) {
        const float* __restrict__ Pm = g_P + ((b*VV + i)*VV + j)*16;
        const float P00 = Pm[0],  P01 = Pm[1],  P02 = Pm[2],  P03 = Pm[3];
        const float P10 = Pm[4],  P11 = Pm[5],  P12 = Pm[6],  P13 = Pm[7];
        const float P20 = Pm[8],  P21 = Pm[9],  P22 = Pm[10], P23 = Pm[11];
        const float* __restrict__ dj = pred + (size_t)(b*VV + j)*NPIX;

        float ln = 0.0f, ld = 0.0f;
#pragma unroll
        for (int k = 0; k < QPT; k++) {
            const float yf = yfv[k], xf0 = xfv[k];
            float ax = fmaf(P00, xf0, fmaf(P01, yf, P02));
            float ay = fmaf(P10, xf0, fmaf(P11, yf, P12));
            const float* dptr = (const float*)&dv[k];
#pragma unroll
            for (int l = 0; l < 4; l++) {
                const float d  = dptr[l];
                const float px = fmaf(d, ax, P03);     // pw == 1 exactly (bottom rows all [0,0,0,1])
                const float py = fmaf(d, ay, P13);
                const float gx = fmaf(px, inv_hw, -1.0f);
                const float gy = fmaf(py, inv_hh, -1.0f);
                if (gx >= -1.0f && gx <= 1.0f && gy >= -1.0f && gy <= 1.0f) {
                    const float xl = xf0 + (float)l;
                    const float az = fmaf(P20, xl, fmaf(P21, yf, P22));
                    const float pz = fmaf(d, az, P23);
                    const float ix = ((gx + 1.0f)*(float)WW - 1.0f)*0.5f;
                    const float iy = ((gy + 1.0f)*(float)HH - 1.0f)*0.5f;
                    const float x0f = floorf(ix), y0f = floorf(iy);
                    const float wx1 = ix - x0f,   wy1 = iy - y0f;
                    const float wx0 = 1.0f - wx1, wy0 = 1.0f - wy1;
                    const int x0 = (int)x0f, y0 = (int)y0f;
                    const float c00 = corner(dj, x0,     y0);
                    const float c10 = corner(dj, x0 + 1, y0);
                    const float c01 = corner(dj, x0,     y0 + 1);
                    const float c11 = corner(dj, x0 + 1, y0 + 1);
                    const float warped = wy0*(wx0*c00 + wx1*c10) + wy1*(wx0*c01 + wx1*c11);
                    ln += fabsf(warped - pz);
                    ld += 1.0f;
                }
                ax += P00;   // projection affine in x
                ay += P10;
            }
        }
        num[j] = ln; den[j] = ld;
    }

    // Block reduce 2*VV values, then 2*VV double atomics per block.
    __shared__ float sred[2*VV][TPB/32];
    const int warp = threadIdx.x >> 5, lane = threadIdx.x & 31;
#pragma unroll
    for (int j = 0; j < VV; j++) {
        float n = num[j], dn = den[j];
#pragma unroll
        for (int o = 16; o > 0; o >>= 1) {
            n  += __shfl_xor_sync(0xFFFFFFFFu, n,  o);
            dn += __shfl_xor_sync(0xFFFFFFFFu, dn, o);
        }
        if (lane == 0) { sred[2*j][warp] = n; sred[2*j+1][warp] = dn; }
    }
    __syncthreads();
    if (warp == 0 && lane < 2*VV*(TPB/32)) {
        // lane layout: value v in [0, 2*VV), warp w in [0, TPB/32)
        // reduce each value's 8 warp-partials; do it simply: first 2*VV lanes own one value each
    }
    if (threadIdx.x < 2*VV) {
        float s = 0.0f;
#pragma unroll
        for (int w = 0; w < TPB/32; w++) s += sred[threadIdx.x][w];
        const int j = threadIdx.x >> 1;
        const int p = (b*VV + i)*VV + j;
        if ((threadIdx.x & 1) == 0) atomicAdd(&g_num[p], (double)s);
        else                        atomicAdd(&g_den[p], (double)s);
    }
}

__global__ void finalize_kernel(float* __restrict__ out) {
    if (threadIdx.x == 0) {
        double t = 0.0;
#pragma unroll
        for (int p = 0; p < NPAIR; p++) {
            double n = 0.0, dn = 0.0;
#pragma unroll
            for (int b = 0; b < BB; b++) {
                n  += g_num[b*NPAIR + p];
                dn += g_den[b*NPAIR + p];
            }
            t += n / (dn > 1.0 ? dn : 1.0);
        }
        out[0] = (float)t;
    }
}

extern "C" void kernel_launch(void* const* d_in, const int* in_sizes, int n_in,
                              void* d_out, int out_size) {
    const float* pred = (const float*)d_in[0];   // (B,V,H,W)
    const float* K    = (const float*)d_in[1];   // (B,4,4)
    const float* RT   = (const float*)d_in[2];   // (B,V,4,4)
    float* out = (float*)d_out;

    setup_kernel<<<1, 128>>>(K, RT);
    loss_kernel<<<dim3(GX, BB, VV), TPB>>>(pred);
    finalize_kernel<<<1, 32>>>(out);
}

// round 5
// speedup vs baseline: 1.1477x; 1.1152x over previous
#include <cuda_runtime.h>
#include <math.h>

#define BB 8
#define VV 3
#define HH 512
#define WW 640
#define NPIX (HH*WW)
#define NPAIR (VV*VV)
#define TPB 256
#define QPT 4                      // float4 quads per thread
#define GX 80                      // 80*256*4 = 81920 quads = NPIX/4
#define QSTRIDE (GX*TPB)
#define QROW (WW/4)
#define NBLOCKS (GX*BB*VV)

__device__ double   g_num[BB*NPAIR];   // zero-init at load; reset by last block each call
__device__ double   g_den[BB*NPAIR];
__device__ unsigned g_count;

__device__ __forceinline__ void mat4mul(const float* A, const float* Bm, float* C) {
#pragma unroll
    for (int r = 0; r < 4; r++)
#pragma unroll
        for (int c = 0; c < 4; c++) {
            float s = 0.0f;
#pragma unroll
            for (int k = 0; k < 4; k++) s = fmaf(A[r*4+k], Bm[k*4+c], s);
            C[r*4+c] = s;
        }
}

// thread-local compute of P[b,i,j] rows 0..2 (12 coeffs) -> out
__device__ __forceinline__ void compute_P(const float* __restrict__ K,
                                          const float* __restrict__ RT,
                                          int b, int i, int j, float* out) {
    const float* Kb  = K  + b*16;
    const float* RTi = RT + (b*VV + i)*16;
    const float* RTj = RT + (b*VV + j)*16;

    float Kinv[16] = {0};
    float fx = Kb[0], fy = Kb[5], cx = Kb[2], cy = Kb[6];
    Kinv[0]  = 1.0f/fx;  Kinv[2]  = -cx/fx;
    Kinv[5]  = 1.0f/fy;  Kinv[6]  = -cy/fy;
    Kinv[10] = 1.0f;     Kinv[15] = 1.0f;

    float Ri[16] = {0};
    Ri[0] = RTi[0]; Ri[1] = RTi[4]; Ri[2]  = RTi[8];
    Ri[4] = RTi[1]; Ri[5] = RTi[5]; Ri[6]  = RTi[9];
    Ri[8] = RTi[2]; Ri[9] = RTi[6]; Ri[10] = RTi[10];
    float tx = RTi[3], ty = RTi[7], tz = RTi[11];
    Ri[3]  = -(Ri[0]*tx + Ri[1]*ty + Ri[2]*tz);
    Ri[7]  = -(Ri[4]*tx + Ri[5]*ty + Ri[6]*tz);
    Ri[11] = -(Ri[8]*tx + Ri[9]*ty + Ri[10]*tz);
    Ri[15] = 1.0f;

    float M1[16], M2[16], Pf[16];
    mat4mul(RTj, Ri, M1);
    mat4mul(M1, Kinv, M2);
    mat4mul(Kb, M2, Pf);
#pragma unroll
    for (int k = 0; k < 12; k++) out[k] = Pf[k];
}

__global__ void __launch_bounds__(TPB)
loss_kernel(const float* __restrict__ pred, const float* __restrict__ K,
            const float* __restrict__ RT, float* __restrict__ out) {
    const int b = blockIdx.y, i = blockIdx.z;

    __shared__ float sP[VV][12];
    if (threadIdx.x < VV)
        compute_P(K, RT, b, i, threadIdx.x, sP[threadIdx.x]);
    __syncthreads();

    const float* __restrict__ di = pred + (size_t)(b*VV + i)*NPIX;

    float4 dv[QPT];
    float  yfv[QPT], xfv[QPT];
    const int q0 = blockIdx.x*TPB + threadIdx.x;
#pragma unroll
    for (int k = 0; k < QPT; k++) {
        int q = q0 + k*QSTRIDE;
        dv[k] = __ldg((const float4*)di + q);
        int yy = q / QROW;
        yfv[k] = (float)yy;
        xfv[k] = (float)((q - yy*QROW) * 4);
    }

    const float XMAX = 639.0f, YMAX = 511.0f;
    const float SXI  = 640.0f/639.0f, SYI = 512.0f/511.0f;

    float num[VV], den[VV];

#pragma unroll
    for (int j = 0; j < VV; j++) {
        const float P00 = sP[j][0], P01 = sP[j][1], P02 = sP[j][2],  P03 = sP[j][3];
        const float P10 = sP[j][4], P11 = sP[j][5], P12 = sP[j][6],  P13 = sP[j][7];
        const float P20 = sP[j][8], P21 = sP[j][9], P22 = sP[j][10], P23 = sP[j][11];
        const float* __restrict__ dj = pred + (size_t)(b*VV + j)*NPIX;

        float ln = 0.0f, ld = 0.0f;
#pragma unroll
        for (int k = 0; k < QPT; k++) {
            const float yf = yfv[k], xf0 = xfv[k];
            float ax = fmaf(P00, xf0, fmaf(P01, yf, P02));
            float ay = fmaf(P10, xf0, fmaf(P11, yf, P12));
            const float* dptr = (const float*)&dv[k];
#pragma unroll
            for (int l = 0; l < 4; l++) {
                const float d  = dptr[l];
                const float px = fmaf(d, ax, P03);  // homogeneous w == 1 exactly
                const float py = fmaf(d, ay, P13);
                if (px >= 0.0f && px <= XMAX && py >= 0.0f && py <= YMAX) {
                    const float az = fmaf(P20, xf0 + (float)l, fmaf(P21, yf, P22));
                    const float pz = fmaf(d, az, P23);
                    const float ix = fmaf(px, SXI, -0.5f);
                    const float iy = fmaf(py, SYI, -0.5f);
                    const float x0f = floorf(ix), y0f = floorf(iy);
                    const float wx1 = ix - x0f,   wy1 = iy - y0f;
                    const float wx0 = 1.0f - wx1, wy0 = 1.0f - wy1;
                    const int x0 = (int)x0f, y0 = (int)y0f;
                    const int base = y0*WW + x0;
                    // validity: x0 in [-1,639], y0 in [-1,511] here
                    const bool vx0 = (unsigned)x0 < (unsigned)WW;       // x0 >= 0 (x0 <= 639 given)
                    const bool vx1 = (unsigned)(x0+1) < (unsigned)WW;
                    const bool vy0 = (unsigned)y0 < (unsigned)HH;
                    const bool vy1 = (unsigned)(y0+1) < (unsigned)HH;
                    const float c00 = (vx0 && vy0) ? __ldg(dj + base)        : 0.0f;
                    const float c10 = (vx1 && vy0) ? __ldg(dj + base + 1)    : 0.0f;
                    const float c01 = (vx0 && vy1) ? __ldg(dj + base + WW)   : 0.0f;
                    const float c11 = (vx1 && vy1) ? __ldg(dj + base + WW+1) : 0.0f;
                    const float warped = wy0*fmaf(wx1, c10 - c00, c00)
                                       + wy1*fmaf(wx1, c11 - c01, c01);
                    ln += fabsf(warped - pz);
                    ld += 1.0f;
                }
                ax += P00;
                ay += P10;
            }
        }
        num[j] = ln; den[j] = ld;
    }

    // block reduce 6 scalars
    __shared__ float sred[2*VV][TPB/32];
    const int warp = threadIdx.x >> 5, lane = threadIdx.x & 31;
#pragma unroll
    for (int j = 0; j < VV; j++) {
        float n = num[j], dn = den[j];
#pragma unroll
        for (int o = 16; o > 0; o >>= 1) {
            n  += __shfl_xor_sync(0xFFFFFFFFu, n,  o);
            dn += __shfl_xor_sync(0xFFFFFFFFu, dn, o);
        }
        if (lane == 0) { sred[2*j][warp] = n; sred[2*j+1][warp] = dn; }
    }
    __syncthreads();
    if (threadIdx.x < 2*VV) {
        float s = 0.0f;
#pragma unroll
        for (int w = 0; w < TPB/32; w++) s += sred[threadIdx.x][w];
        const int j = threadIdx.x >> 1;
        const int p = (b*VV + i)*VV + j;
        if ((threadIdx.x & 1) == 0) atomicAdd(&g_num[p], (double)s);
        else                        atomicAdd(&g_den[p], (double)s);
    }
    __syncthreads();

    // last-block finalize
    __shared__ bool s_last;
    if (threadIdx.x == 0) {
        __threadfence();
        s_last = (atomicAdd(&g_count, 1u) == (unsigned)(NBLOCKS - 1));
    }
    __syncthreads();
    if (s_last && threadIdx.x == 0) {
        double t = 0.0;
#pragma unroll
        for (int p = 0; p < NPAIR; p++) {
            double n = 0.0, dn = 0.0;
#pragma unroll
            for (int bb = 0; bb < BB; bb++) {
                n  += g_num[bb*NPAIR + p];
                dn += g_den[bb*NPAIR + p];
            }
            t += n / (dn > 1.0 ? dn : 1.0);
        }
        out[0] = (float)t;
        // reset for next graph replay
#pragma unroll
        for (int p = 0; p < BB*NPAIR; p++) { g_num[p] = 0.0; g_den[p] = 0.0; }
        __threadfence();
        g_count = 0u;
    }
}

extern "C" void kernel_launch(void* const* d_in, const int* in_sizes, int n_in,
                              void* d_out, int out_size) {
    const float* pred = (const float*)d_in[0];   // (B,V,H,W)
    const float* K    = (const float*)d_in[1];   // (B,4,4)
    const float* RT   = (const float*)d_in[2];   // (B,V,4,4)
    loss_kernel<<<dim3(GX, BB, VV), TPB>>>(pred, K, RT, (float*)d_out);
}

// round 6
// speedup vs baseline: 1.2638x; 1.1012x over previous
#include <cuda_runtime.h>
#include <math.h>

#define BB 8
#define VV 3
#define HH 512
#define WW 640
#define NPIX (HH*WW)
#define NPAIR (VV*VV)
#define TPB 256
#define QPT 4                      // float4 quads per thread
#define GX 80                      // 80*256 = 20480 quads/pass = exactly 128 rows
#define QSTRIDE (GX*TPB)           // 20480 quads = 128 rows
#define ROWSTEP 128
#define QROW (WW/4)                // 160
#define NBLOCKS (GX*BB*VV)

__device__ double   g_num[BB*NPAIR];
__device__ double   g_den[BB*NPAIR];
__device__ unsigned g_count;

__device__ __forceinline__ void mat4mul(const float* A, const float* Bm, float* C) {
#pragma unroll
    for (int r = 0; r < 4; r++)
#pragma unroll
        for (int c = 0; c < 4; c++) {
            float s = 0.0f;
#pragma unroll
            for (int k = 0; k < 4; k++) s = fmaf(A[r*4+k], Bm[k*4+c], s);
            C[r*4+c] = s;
        }
}

__device__ __forceinline__ void compute_P(const float* __restrict__ K,
                                          const float* __restrict__ RT,
                                          int b, int i, int j, float* out) {
    const float* Kb  = K  + b*16;
    const float* RTi = RT + (b*VV + i)*16;
    const float* RTj = RT + (b*VV + j)*16;

    float Kinv[16] = {0};
    float fx = Kb[0], fy = Kb[5], cx = Kb[2], cy = Kb[6];
    Kinv[0]  = 1.0f/fx;  Kinv[2]  = -cx/fx;
    Kinv[5]  = 1.0f/fy;  Kinv[6]  = -cy/fy;
    Kinv[10] = 1.0f;     Kinv[15] = 1.0f;

    float Ri[16] = {0};
    Ri[0] = RTi[0]; Ri[1] = RTi[4]; Ri[2]  = RTi[8];
    Ri[4] = RTi[1]; Ri[5] = RTi[5]; Ri[6]  = RTi[9];
    Ri[8] = RTi[2]; Ri[9] = RTi[6]; Ri[10] = RTi[10];
    float tx = RTi[3], ty = RTi[7], tz = RTi[11];
    Ri[3]  = -(Ri[0]*tx + Ri[1]*ty + Ri[2]*tz);
    Ri[7]  = -(Ri[4]*tx + Ri[5]*ty + Ri[6]*tz);
    Ri[11] = -(Ri[8]*tx + Ri[9]*ty + Ri[10]*tz);
    Ri[15] = 1.0f;

    float M1[16], M2[16], Pf[16];
    mat4mul(RTj, Ri, M1);
    mat4mul(M1, Kinv, M2);
    mat4mul(Kb, M2, Pf);
#pragma unroll
    for (int k = 0; k < 12; k++) out[k] = Pf[k];
}

__global__ void __launch_bounds__(TPB, 6)
loss_kernel(const float* __restrict__ pred, const float* __restrict__ K,
            const float* __restrict__ RT, float* __restrict__ out) {
    const int b = blockIdx.y, i = blockIdx.z;

    __shared__ float sP[VV][12];
    if (threadIdx.x < VV)
        compute_P(K, RT, b, i, threadIdx.x, sP[threadIdx.x]);
    __syncthreads();

    const float* __restrict__ di = pred + (size_t)(b*VV + i)*NPIX;
    const float* __restrict__ dj0 = pred + (size_t)(b*VV + 0)*NPIX;

    // One decode per thread; subsequent quads are exactly +128 rows, same x.
    const int q0  = blockIdx.x*TPB + threadIdx.x;
    const int yy0 = q0 / QROW;
    const float xf0 = (float)((q0 - yy0*QROW) * 4);

    const float XMAX = 639.0f, YMAX = 511.0f;
    const float SXI  = 640.0f/639.0f, SYI = 512.0f/511.0f;

    float num[VV] = {0.f, 0.f, 0.f};
    float den[VV] = {0.f, 0.f, 0.f};

#pragma unroll
    for (int k = 0; k < QPT; k++) {
        const int q = q0 + k*QSTRIDE;
        const float4 dvq = __ldg((const float4*)di + q);
        const float yf = (float)(yy0 + k*ROWSTEP);
        const float* dptr = (const float*)&dvq;

#pragma unroll
        for (int j = 0; j < VV; j++) {
            const float P00 = sP[j][0], P01 = sP[j][1], P02 = sP[j][2],  P03 = sP[j][3];
            const float P10 = sP[j][4], P11 = sP[j][5], P12 = sP[j][6],  P13 = sP[j][7];
            const float P20 = sP[j][8], P21 = sP[j][9], P22 = sP[j][10], P23 = sP[j][11];
            const float* __restrict__ dj = dj0 + (size_t)j*NPIX;

            float ax = fmaf(P00, xf0, fmaf(P01, yf, P02));
            float ay = fmaf(P10, xf0, fmaf(P11, yf, P12));
            float ln = 0.0f, ld = 0.0f;
#pragma unroll
            for (int l = 0; l < 4; l++) {
                const float d  = dptr[l];
                const float px = fmaf(d, ax, P03);   // homogeneous w == 1 exactly
                const float py = fmaf(d, ay, P13);
                if (px >= 0.0f && px <= XMAX && py >= 0.0f && py <= YMAX) {
                    const float az = fmaf(P20, xf0 + (float)l, fmaf(P21, yf, P22));
                    const float pz = fmaf(d, az, P23);
                    const float ix = fmaf(px, SXI, -0.5f);
                    const float iy = fmaf(py, SYI, -0.5f);
                    const float x0f = floorf(ix), y0f = floorf(iy);
                    const float wx1 = ix - x0f,   wy1 = iy - y0f;
                    const int x0 = (int)x0f, y0 = (int)y0f;
                    const int base = y0*WW + x0;
                    const bool vx0 = (unsigned)x0 < (unsigned)WW;
                    const bool vx1 = (unsigned)(x0+1) < (unsigned)WW;
                    const bool vy0 = (unsigned)y0 < (unsigned)HH;
                    const bool vy1 = (unsigned)(y0+1) < (unsigned)HH;
                    const float c00 = (vx0 && vy0) ? __ldg(dj + base)        : 0.0f;
                    const float c10 = (vx1 && vy0) ? __ldg(dj + base + 1)    : 0.0f;
                    const float c01 = (vx0 && vy1) ? __ldg(dj + base + WW)   : 0.0f;
                    const float c11 = (vx1 && vy1) ? __ldg(dj + base + WW+1) : 0.0f;
                    const float warped = (1.0f - wy1)*fmaf(wx1, c10 - c00, c00)
                                       + wy1*fmaf(wx1, c11 - c01, c01);
                    ln += fabsf(warped - pz);
                    ld += 1.0f;
                }
                ax += P00;
                ay += P10;
            }
            num[j] += ln; den[j] += ld;
        }
    }

    // block reduce 6 scalars
    __shared__ float sred[2*VV][TPB/32];
    const int warp = threadIdx.x >> 5, lane = threadIdx.x & 31;
#pragma unroll
    for (int j = 0; j < VV; j++) {
        float n = num[j], dn = den[j];
#pragma unroll
        for (int o = 16; o > 0; o >>= 1) {
            n  += __shfl_xor_sync(0xFFFFFFFFu, n,  o);
            dn += __shfl_xor_sync(0xFFFFFFFFu, dn, o);
        }
        if (lane == 0) { sred[2*j][warp] = n; sred[2*j+1][warp] = dn; }
    }
    __syncthreads();
    if (threadIdx.x < 2*VV) {
        float s = 0.0f;
#pragma unroll
        for (int w = 0; w < TPB/32; w++) s += sred[threadIdx.x][w];
        const int j = threadIdx.x >> 1;
        const int p = (b*VV + i)*VV + j;
        if ((threadIdx.x & 1) == 0) atomicAdd(&g_num[p], (double)s);
        else                        atomicAdd(&g_den[p], (double)s);
    }
    __syncthreads();

    // last-block finalize
    __shared__ bool s_last;
    if (threadIdx.x == 0) {
        __threadfence();
        s_last = (atomicAdd(&g_count, 1u) == (unsigned)(NBLOCKS - 1));
    }
    __syncthreads();
    if (s_last && threadIdx.x == 0) {
        double t = 0.0;
#pragma unroll
        for (int p = 0; p < NPAIR; p++) {
            double n = 0.0, dn = 0.0;
#pragma unroll
            for (int bb = 0; bb < BB; bb++) {
                n  += g_num[bb*NPAIR + p];
                dn += g_den[bb*NPAIR + p];
            }
            t += n / (dn > 1.0 ? dn : 1.0);
        }
        out[0] = (float)t;
#pragma unroll
        for (int p = 0; p < BB*NPAIR; p++) { g_num[p] = 0.0; g_den[p] = 0.0; }
        __threadfence();
        g_count = 0u;
    }
}

extern "C" void kernel_launch(void* const* d_in, const int* in_sizes, int n_in,
                              void* d_out, int out_size) {
    const float* pred = (const float*)d_in[0];   // (B,V,H,W)
    const float* K    = (const float*)d_in[1];   // (B,4,4)
    const float* RT   = (const float*)d_in[2];   // (B,V,4,4)
    loss_kernel<<<dim3(GX, BB, VV), TPB>>>(pred, K, RT, (float*)d_out);
}